// round 1
// baseline (speedup 1.0000x reference)
#include <cuda_runtime.h>
#include <cstdint>
#include <math.h>

// Problem constants
#define BB 16
#define TT 2048
#define CC 512
#define HH 4
#define NT (BB*TT)     // 32768 tokens
#define RR (NT*2)      // 65536 rows (token,device)
#define JJ 1536        // q|k|v packed

// ---------------- scratch (static device memory; no allocation) ----------------
__device__ float g_qkv[(size_t)RR * JJ];     // 402 MB
__device__ float g_ctx[(size_t)NT * 1024];   // 134 MB  (ctx0|ctx1 per token)
__device__ float g_WoT[CC*CC];
__device__ float g_G0[CC*CC];
__device__ float g_G1[CC*CC];
__device__ float g_GT0[CC*CC];
__device__ float g_GT1[CC*CC];
__device__ float g_M[CC*1024];               // [o][j<512]=M0, [o][512+j]=M1
__device__ float g_bc[CC];
__device__ float g_qb[2*JJ];
__device__ float g_ucat[1024];
__device__ float g_att[BB*4];

// ---------------- helpers ----------------
__device__ __forceinline__ float warp_sum(float v) {
#pragma unroll
    for (int o = 16; o > 0; o >>= 1) v += __shfl_xor_sync(0xffffffffu, v, o);
    return v;
}

__device__ __forceinline__ uint32_t f2tf32(float f) {
    uint32_t u;
    asm("cvt.rna.tf32.f32 %0, %1;" : "=r"(u) : "f"(f));
    return u;
}

__device__ __forceinline__ void mma_tf32(float* c, const uint32_t* a, const uint32_t* b) {
    asm volatile(
        "mma.sync.aligned.m16n8k8.row.col.f32.tf32.tf32.f32 "
        "{%0,%1,%2,%3}, {%4,%5,%6,%7}, {%8,%9}, {%0,%1,%2,%3};\n"
        : "+f"(c[0]), "+f"(c[1]), "+f"(c[2]), "+f"(c[3])
        : "r"(a[0]), "r"(a[1]), "r"(a[2]), "r"(a[3]), "r"(b[0]), "r"(b[1]));
}

// ---------------- small prep kernels ----------------
__global__ void zero_att_kernel() {
    if (threadIdx.x < BB*4) g_att[threadIdx.x] = 0.f;
}

// qb[d*1536+j] = in_proj_b[j] + sum_c emb[d][c] * W1[j][c]
__global__ void qb_kernel(const float* __restrict__ W1, const float* __restrict__ b1,
                          const float* __restrict__ emb) {
    int widx = (blockIdx.x * blockDim.x + threadIdx.x) >> 5;
    int lane = threadIdx.x & 31;
    if (widx >= 2 * JJ) return;
    int d = widx / JJ, j = widx % JJ;
    const float* wrow = W1 + (long)j * CC;
    const float* e = emb + d * CC;
    float s = 0.f;
    for (int c = lane; c < CC; c += 32) s += wrow[c] * e[c];
    s = warp_sum(s);
    if (lane == 0) g_qb[widx] = b1[j] + s;
}

// ucat[k<512] = bp[k] + Wp[k]·bo ; ucat[512+k] = bi[k] + Wi[k]·bo
__global__ void ub_kernel(const float* __restrict__ Wp, const float* __restrict__ bp,
                          const float* __restrict__ Wi, const float* __restrict__ bi,
                          const float* __restrict__ bo) {
    int widx = (blockIdx.x * blockDim.x + threadIdx.x) >> 5;
    int lane = threadIdx.x & 31;
    if (widx >= 1024) return;
    const float* wrow;
    float bias;
    if (widx < CC) { wrow = Wp + (long)widx * CC; bias = bp[widx]; }
    else           { wrow = Wi + (long)(widx - CC) * CC; bias = bi[widx - CC]; }
    float s = 0.f;
    for (int c = lane; c < CC; c += 32) s += wrow[c] * bo[c];
    s = warp_sum(s);
    if (lane == 0) g_ucat[widx] = bias + s;
}

// bc[o] = bout[o] + sum_{k<1024} output_w[o][k] * ucat[k]
__global__ void bc_kernel(const float* __restrict__ Wout, const float* __restrict__ bout) {
    int widx = (blockIdx.x * blockDim.x + threadIdx.x) >> 5;
    int lane = threadIdx.x & 31;
    if (widx >= CC) return;
    const float* wrow = Wout + (long)widx * 1024;
    float s = 0.f;
    for (int c = lane; c < 1024; c += 32) s += wrow[c] * g_ucat[c];
    s = warp_sum(s);
    if (lane == 0) g_bc[widx] = bout[widx] + s;
}

__global__ void transpose512(const float* __restrict__ src, float* __restrict__ dst) {
    __shared__ float tile[32][33];
    int x = blockIdx.x * 32 + threadIdx.x;
    int y = blockIdx.y * 32 + threadIdx.y;
#pragma unroll
    for (int i = 0; i < 32; i += 8)
        tile[threadIdx.y + i][threadIdx.x] = src[(long)(y + i) * 512 + x];
    __syncthreads();
    x = blockIdx.y * 32 + threadIdx.x;
    y = blockIdx.x * 32 + threadIdx.y;
#pragma unroll
    for (int i = 0; i < 32; i += 8)
        dst[(long)(y + i) * 512 + x] = tile[threadIdx.x][threadIdx.y + i];
}

__global__ void avg_out_kernel(float* __restrict__ dst) {
    if (threadIdx.x < BB*4) dst[threadIdx.x] = g_att[threadIdx.x] * (1.0f / (float)TT);
}

// ---------------- main tf32 GEMM: C = A * B^T ----------------
// MODE 0 (FOLD): A row-major (k-contig, lda), plain store (ldc)
// MODE 1 (QKV):  A = x (B,C,2,T) m-contig; epilogue adds per-device qb bias; store g_qkv
// MODE 2 (OUT):  A row-major k-contig; epilogue adds bc and stores transposed to (B,C,T)
// Tiles: BM=BN=128, BK=16, 512 threads (4x4 warps of 32x32), double-buffered smem.
enum { M_FOLD = 0, M_QKV = 1, M_OUT = 2 };

template<int MODE>
__global__ __launch_bounds__(512)
void gemm_tf32(const float* __restrict__ A, const float* __restrict__ Bm,
               float* __restrict__ Cp, const float* __restrict__ bias,
               int K, int lda, int ldb, int ldc)
{
    __shared__ uint32_t As[2][16][136];   // padded: conflict-free frag reads
    __shared__ uint32_t Bs[2][128][20];

    const int tid  = threadIdx.x;
    const int lane = tid & 31;
    const int warp = tid >> 5;
    const int wm = warp & 3;
    const int wn = warp >> 2;
    const int bn = blockIdx.x;
    const int bm = blockIdx.y;

    const float* aPtr;
    long aStep;
    int a_k, a_m;
    if (MODE == M_QKV) {
        // rows r = (2b+d)*T + t ; x element (b,c,d,t) at ((b*C+c)*2+d)*T + t
        int r0 = bm * 128;
        int t0 = r0 & (TT - 1);
        int bd = r0 >> 11;
        const float* Abase = A + (long)(bd >> 1) * (2L * CC * TT) + (long)(bd & 1) * TT + t0;
        a_k = tid >> 5;           // 0..15
        a_m = (tid & 31) << 2;    // 0..124
        aPtr = Abase + (long)a_k * (2 * TT) + a_m;
        aStep = 16L * (2 * TT);
    } else {
        a_m = tid >> 2;           // 0..127
        a_k = (tid & 3) << 2;     // 0,4,8,12
        aPtr = A + (long)(bm * 128 + a_m) * lda + a_k;
        aStep = 16;
    }
    const int b_n = tid >> 2;
    const int b_k = (tid & 3) << 2;
    const float* bPtr = Bm + (long)(bn * 128 + b_n) * ldb + b_k;

    float c[2][4][4];
#pragma unroll
    for (int i = 0; i < 2; ++i)
#pragma unroll
        for (int j = 0; j < 4; ++j)
#pragma unroll
            for (int q = 0; q < 4; ++q) c[i][j][q] = 0.f;

    float4 aReg = *(const float4*)aPtr; aPtr += aStep;
    float4 bReg = *(const float4*)bPtr; bPtr += 16;

    // stage tile 0
    {
        uint32_t a0 = f2tf32(aReg.x), a1 = f2tf32(aReg.y), a2 = f2tf32(aReg.z), a3 = f2tf32(aReg.w);
        if (MODE == M_QKV) {
            *(uint4*)&As[0][a_k][a_m] = make_uint4(a0, a1, a2, a3);
        } else {
            As[0][a_k + 0][a_m] = a0; As[0][a_k + 1][a_m] = a1;
            As[0][a_k + 2][a_m] = a2; As[0][a_k + 3][a_m] = a3;
        }
        *(uint4*)&Bs[0][b_n][b_k] =
            make_uint4(f2tf32(bReg.x), f2tf32(bReg.y), f2tf32(bReg.z), f2tf32(bReg.w));
    }
    __syncthreads();

    const int KT = K >> 4;
    for (int kt = 0; kt < KT; ++kt) {
        const int cur = kt & 1;
        const bool more = (kt + 1) < KT;
        if (more) {
            aReg = *(const float4*)aPtr; aPtr += aStep;
            bReg = *(const float4*)bPtr; bPtr += 16;
        }
#pragma unroll
        for (int k0 = 0; k0 < 16; k0 += 8) {
            uint32_t af[2][4];
            uint32_t bf[4][2];
            const int kk = k0 + (lane & 3);
            const int mr = wm * 32 + (lane >> 2);
#pragma unroll
            for (int ms = 0; ms < 2; ++ms) {
                const int m = mr + ms * 16;
                af[ms][0] = As[cur][kk][m];
                af[ms][1] = As[cur][kk][m + 8];
                af[ms][2] = As[cur][kk + 4][m];
                af[ms][3] = As[cur][kk + 4][m + 8];
            }
#pragma unroll
            for (int ns = 0; ns < 4; ++ns) {
                const int n = wn * 32 + ns * 8 + (lane >> 2);
                bf[ns][0] = Bs[cur][n][kk];
                bf[ns][1] = Bs[cur][n][kk + 4];
            }
#pragma unroll
            for (int ms = 0; ms < 2; ++ms)
#pragma unroll
                for (int ns = 0; ns < 4; ++ns)
                    mma_tf32(c[ms][ns], af[ms], bf[ns]);
        }
        if (more) {
            const int nxt = cur ^ 1;
            uint32_t a0 = f2tf32(aReg.x), a1 = f2tf32(aReg.y), a2 = f2tf32(aReg.z), a3 = f2tf32(aReg.w);
            if (MODE == M_QKV) {
                *(uint4*)&As[nxt][a_k][a_m] = make_uint4(a0, a1, a2, a3);
            } else {
                As[nxt][a_k + 0][a_m] = a0; As[nxt][a_k + 1][a_m] = a1;
                As[nxt][a_k + 2][a_m] = a2; As[nxt][a_k + 3][a_m] = a3;
            }
            *(uint4*)&Bs[nxt][b_n][b_k] =
                make_uint4(f2tf32(bReg.x), f2tf32(bReg.y), f2tf32(bReg.z), f2tf32(bReg.w));
        }
        __syncthreads();
    }

    // epilogue
    const int row0 = bm * 128 + wm * 32 + (lane >> 2);
    const int col0 = bn * 128 + wn * 32 + ((lane & 3) << 1);
#pragma unroll
    for (int ms = 0; ms < 2; ++ms) {
#pragma unroll
        for (int ns = 0; ns < 4; ++ns) {
            const int r   = row0 + ms * 16;
            const int col = col0 + ns * 8;
            const float v0 = c[ms][ns][0], v1 = c[ms][ns][1];
            const float v2 = c[ms][ns][2], v3 = c[ms][ns][3];
            if (MODE == M_FOLD) {
                *(float2*)&Cp[(long)r * ldc + col]       = make_float2(v0, v1);
                *(float2*)&Cp[(long)(r + 8) * ldc + col] = make_float2(v2, v3);
            } else if (MODE == M_QKV) {
                const int dd = (bm >> 4) & 1;
                const float bb0 = bias[dd * JJ + col];
                const float bb1 = bias[dd * JJ + col + 1];
                *(float2*)&Cp[(long)r * ldc + col]       = make_float2(v0 + bb0, v1 + bb1);
                *(float2*)&Cp[(long)(r + 8) * ldc + col] = make_float2(v2 + bb0, v3 + bb1);
            } else { // M_OUT: out[(b*C+col)*T + t]
                const int b_ = r >> 11;
                const int t_ = r & (TT - 1);
                const float bb0 = bias[col], bb1 = bias[col + 1];
                float* o0 = Cp + (long)(b_ * CC + col) * TT + t_;
                float* o1 = Cp + (long)(b_ * CC + col + 1) * TT + t_;
                o0[0] = v0 + bb0; o1[0] = v1 + bb1;
                o0[8] = v2 + bb0; o1[8] = v3 + bb1;
            }
        }
    }
}

// ---------------- attention (2x2 per head) + ctx + avg-attention ----------------
__global__ void attn_kernel()
{
    const int warp = threadIdx.x >> 5;
    const int lane = threadIdx.x & 31;
    const int n = blockIdx.x * 8 + warp;      // token
    const int b = n >> 11;
    const int t = n & (TT - 1);
    const float* row0 = g_qkv + ((long)(b * 2 + 0) * TT + t) * JJ;
    const float* row1 = g_qkv + ((long)(b * 2 + 1) * TT + t) * JJ;

    float s[4][2][2];
#pragma unroll
    for (int h = 0; h < 4; ++h) {
        float q0[4], q1[4], k0[4], k1[4];
#pragma unroll
        for (int j = 0; j < 4; ++j) {
            const int idx = h * 128 + lane + 32 * j;
            q0[j] = row0[idx];        q1[j] = row1[idx];
            k0[j] = row0[512 + idx];  k1[j] = row1[512 + idx];
        }
        float s00 = 0, s01 = 0, s10 = 0, s11 = 0;
#pragma unroll
        for (int j = 0; j < 4; ++j) {
            s00 += q0[j] * k0[j]; s01 += q0[j] * k1[j];
            s10 += q1[j] * k0[j]; s11 += q1[j] * k1[j];
        }
        s[h][0][0] = s00; s[h][0][1] = s01; s[h][1][0] = s10; s[h][1][1] = s11;
    }
#pragma unroll
    for (int h = 0; h < 4; ++h)
#pragma unroll
        for (int d = 0; d < 2; ++d)
#pragma unroll
            for (int e = 0; e < 2; ++e)
                s[h][d][e] = warp_sum(s[h][d][e]);

    const float scale = 0.0883883476483184f;  // 1/sqrt(128)
    float p[4][2][2];
#pragma unroll
    for (int h = 0; h < 4; ++h)
#pragma unroll
        for (int d = 0; d < 2; ++d) {
            const float a  = s[h][d][0] * scale;
            const float bb = s[h][d][1] * scale;
            const float mx = fmaxf(a, bb);
            const float e0 = expf(a - mx), e1 = expf(bb - mx);
            const float inv = 1.0f / (e0 + e1);
            p[h][d][0] = e0 * inv; p[h][d][1] = e1 * inv;
        }

    const float* v0 = row0 + 1024;
    const float* v1 = row1 + 1024;
    float* crow = g_ctx + (long)n * 1024;
#pragma unroll
    for (int u = 0; u < 16; ++u) {
        const int j = lane + 32 * u;
        const int h = j >> 7;
        const float a0 = v0[j], a1 = v1[j];
        crow[j]       = p[h][0][0] * a0 + p[h][0][1] * a1;
        crow[512 + j] = p[h][1][0] * a0 + p[h][1][1] * a1;
    }

    __shared__ float red[8][4];
    if (lane == 0) {
#pragma unroll
        for (int d = 0; d < 2; ++d)
#pragma unroll
            for (int e = 0; e < 2; ++e)
                red[warp][d * 2 + e] =
                    0.25f * (p[0][d][e] + p[1][d][e] + p[2][d][e] + p[3][d][e]);
    }
    __syncthreads();
    if (threadIdx.x < 4) {
        float acc = 0.f;
#pragma unroll
        for (int w = 0; w < 8; ++w) acc += red[w][threadIdx.x];
        atomicAdd(&g_att[b * 4 + threadIdx.x], acc);
    }
}

// ---------------- launch ----------------
extern "C" void kernel_launch(void* const* d_in, const int* in_sizes, int n_in,
                              void* d_out, int out_size)
{
    const float* x    = (const float*)d_in[0];
    const float* emb  = (const float*)d_in[1];
    const float* W1   = (const float*)d_in[2];
    const float* b1   = (const float*)d_in[3];
    const float* Wo   = (const float*)d_in[4];
    const float* bo   = (const float*)d_in[5];
    const float* Wp   = (const float*)d_in[6];
    const float* bp   = (const float*)d_in[7];
    const float* Wi   = (const float*)d_in[8];
    const float* bi   = (const float*)d_in[9];
    const float* Wout = (const float*)d_in[10];
    const float* bout = (const float*)d_in[11];
    float* out = (float*)d_out;

    void *p;
    float *p_WoT, *p_G0, *p_G1, *p_GT0, *p_GT1, *p_M, *p_bc, *p_qb, *p_qkv, *p_ctx;
    cudaGetSymbolAddress(&p, g_WoT); p_WoT = (float*)p;
    cudaGetSymbolAddress(&p, g_G0);  p_G0  = (float*)p;
    cudaGetSymbolAddress(&p, g_G1);  p_G1  = (float*)p;
    cudaGetSymbolAddress(&p, g_GT0); p_GT0 = (float*)p;
    cudaGetSymbolAddress(&p, g_GT1); p_GT1 = (float*)p;
    cudaGetSymbolAddress(&p, g_M);   p_M   = (float*)p;
    cudaGetSymbolAddress(&p, g_bc);  p_bc  = (float*)p;
    cudaGetSymbolAddress(&p, g_qb);  p_qb  = (float*)p;
    cudaGetSymbolAddress(&p, g_qkv); p_qkv = (float*)p;
    cudaGetSymbolAddress(&p, g_ctx); p_ctx = (float*)p;

    zero_att_kernel<<<1, 64>>>();

    // biases
    qb_kernel<<<384, 256>>>(W1, b1, emb);
    ub_kernel<<<128, 256>>>(Wp, bp, Wi, bi, bo);
    bc_kernel<<<64, 256>>>(Wout, bout);

    // fold M0 = WoutL*Wp*Wo, M1 = WoutR*Wi*Wo  (A*B^T primitive + transposes)
    transpose512<<<dim3(16, 16), dim3(32, 8)>>>(Wo, p_WoT);
    gemm_tf32<M_FOLD><<<dim3(4, 4), 512>>>(Wp, p_WoT, p_G0, nullptr, 512, 512, 512, 512);
    gemm_tf32<M_FOLD><<<dim3(4, 4), 512>>>(Wi, p_WoT, p_G1, nullptr, 512, 512, 512, 512);
    transpose512<<<dim3(16, 16), dim3(32, 8)>>>(p_G0, p_GT0);
    transpose512<<<dim3(16, 16), dim3(32, 8)>>>(p_G1, p_GT1);
    gemm_tf32<M_FOLD><<<dim3(4, 4), 512>>>(Wout,       p_GT0, p_M,       nullptr, 512, 1024, 512, 1024);
    gemm_tf32<M_FOLD><<<dim3(4, 4), 512>>>(Wout + 512, p_GT1, p_M + 512, nullptr, 512, 1024, 512, 1024);

    // QKV = x * W1^T + qb   (rows = (2b+d)*T + t)
    gemm_tf32<M_QKV><<<dim3(12, 512), 512>>>(x, W1, p_qkv, p_qb, 512, 0, 512, JJ);

    // attention -> ctx (N x 1024), avg-attention accumulation
    attn_kernel<<<4096, 256>>>();

    // out = ctx * Mcat^T + bc, stored transposed to (B, C, T)
    gemm_tf32<M_OUT><<<dim3(4, 256), 512>>>(p_ctx, p_M, out, p_bc, 1024, 1024, 1024, 0);

    // avg_attention tail (B,2,2), if present in output buffer
    if (out_size >= BB * CC * TT + BB * 4) {
        avg_out_kernel<<<1, 64>>>(out + (long)BB * CC * TT);
    }
}

// round 5
// speedup vs baseline: 1.3696x; 1.3696x over previous
#include <cuda_runtime.h>
#include <cuda_fp16.h>
#include <cstdint>
#include <math.h>

// Problem constants
#define BB 16
#define TT 2048
#define CC 512
#define NT (BB*TT)     // 32768 tokens
#define RR (NT*2)      // 65536 rows (token,device)
#define JJ 1536        // q|k|v packed

// ---------------- scratch (static device memory; no allocation) ----------------
__device__ float g_qkv[(size_t)RR * JJ];     // 402 MB
__device__ float g_ctx[(size_t)NT * 1024];   // 134 MB
__device__ float g_WoT[CC*CC];
__device__ float g_G0[CC*CC];
__device__ float g_G1[CC*CC];
__device__ float g_GT0[CC*CC];
__device__ float g_GT1[CC*CC];
__device__ float g_M[CC*1024];
__device__ float g_bc[CC];
__device__ float g_qb[2*JJ];
__device__ float g_ucat[1024];
__device__ float g_att[BB*4];

// ---------------- helpers ----------------
__device__ __forceinline__ float warp_sum(float v) {
#pragma unroll
    for (int o = 16; o > 0; o >>= 1) v += __shfl_xor_sync(0xffffffffu, v, o);
    return v;
}

__device__ __forceinline__ uint32_t packh2(float lo, float hi) {
    __half2 h = __floats2half2_rn(lo, hi);
    return *(uint32_t*)&h;
}

__device__ __forceinline__ void mma_f16(float* c, const uint32_t* a, const uint32_t* b) {
    asm volatile(
        "mma.sync.aligned.m16n8k16.row.col.f32.f16.f16.f32 "
        "{%0,%1,%2,%3}, {%4,%5,%6,%7}, {%8,%9}, {%0,%1,%2,%3};\n"
        : "+f"(c[0]), "+f"(c[1]), "+f"(c[2]), "+f"(c[3])
        : "r"(a[0]), "r"(a[1]), "r"(a[2]), "r"(a[3]), "r"(b[0]), "r"(b[1]));
}

// ---------------- small prep kernels ----------------
__global__ void zero_att_kernel() {
    if (threadIdx.x < BB*4) g_att[threadIdx.x] = 0.f;
}

// qb[d*1536+j] = in_proj_b[j] + sum_c emb[d][c] * W1[j][c]
__global__ void qb_kernel(const float* __restrict__ W1, const float* __restrict__ b1,
                          const float* __restrict__ emb) {
    int widx = (blockIdx.x * blockDim.x + threadIdx.x) >> 5;
    int lane = threadIdx.x & 31;
    if (widx >= 2 * JJ) return;
    int d = widx / JJ, j = widx % JJ;
    const float* wrow = W1 + (long)j * CC;
    const float* e = emb + d * CC;
    float s = 0.f;
    for (int c = lane; c < CC; c += 32) s += wrow[c] * e[c];
    s = warp_sum(s);
    if (lane == 0) g_qb[widx] = b1[j] + s;
}

// ucat[k<512] = bp[k] + Wp[k]·bo ; ucat[512+k] = bi[k] + Wi[k]·bo
__global__ void ub_kernel(const float* __restrict__ Wp, const float* __restrict__ bp,
                          const float* __restrict__ Wi, const float* __restrict__ bi,
                          const float* __restrict__ bo) {
    int widx = (blockIdx.x * blockDim.x + threadIdx.x) >> 5;
    int lane = threadIdx.x & 31;
    if (widx >= 1024) return;
    const float* wrow;
    float bias;
    if (widx < CC) { wrow = Wp + (long)widx * CC; bias = bp[widx]; }
    else           { wrow = Wi + (long)(widx - CC) * CC; bias = bi[widx - CC]; }
    float s = 0.f;
    for (int c = lane; c < CC; c += 32) s += wrow[c] * bo[c];
    s = warp_sum(s);
    if (lane == 0) g_ucat[widx] = bias + s;
}

// bc[o] = bout[o] + sum_{k<1024} output_w[o][k] * ucat[k]
__global__ void bc_kernel(const float* __restrict__ Wout, const float* __restrict__ bout) {
    int widx = (blockIdx.x * blockDim.x + threadIdx.x) >> 5;
    int lane = threadIdx.x & 31;
    if (widx >= CC) return;
    const float* wrow = Wout + (long)widx * 1024;
    float s = 0.f;
    for (int c = lane; c < 1024; c += 32) s += wrow[c] * g_ucat[c];
    s = warp_sum(s);
    if (lane == 0) g_bc[widx] = bout[widx] + s;
}

__global__ void transpose512(const float* __restrict__ src, float* __restrict__ dst) {
    __shared__ float tile[32][33];
    int x = blockIdx.x * 32 + threadIdx.x;
    int y = blockIdx.y * 32 + threadIdx.y;
#pragma unroll
    for (int i = 0; i < 32; i += 8)
        tile[threadIdx.y + i][threadIdx.x] = src[(long)(y + i) * 512 + x];
    __syncthreads();
    x = blockIdx.y * 32 + threadIdx.x;
    y = blockIdx.x * 32 + threadIdx.y;
#pragma unroll
    for (int i = 0; i < 32; i += 8)
        dst[(long)(y + i) * 512 + x] = tile[threadIdx.x][threadIdx.y + i];
}

__global__ void avg_out_kernel(float* __restrict__ dst) {
    if (threadIdx.x < BB*4) dst[threadIdx.x] = g_att[threadIdx.x] * (1.0f / (float)TT);
}

// ---------------- fp16 tensor GEMM: C = A * B^T (fp32 in/out, fp32 accum) ----------------
// MODE 0 (FOLD): A row-major (k-contig, lda), plain store (ldc)
// MODE 1 (QKV):  A = x (B,C,2,T) m-contig; epilogue adds per-device qb bias
// MODE 2 (OUT):  A row-major; epilogue adds bc and stores transposed to (B,C,T)
// Tiles: BM=BN=128, BK=32, 512 threads (4x4 warps, warp tile 32x32).
// Smem: half2 pairs along k: As2[k2][m], row stride 136 words -> conflict-free
// fragment reads (bank = g + 8q, all distinct).
enum { M_FOLD = 0, M_QKV = 1, M_OUT = 2 };

template<int MODE>
__global__ __launch_bounds__(512)
void gemm_h(const float* __restrict__ A, const float* __restrict__ Bm,
            float* __restrict__ Cp, const float* __restrict__ bias,
            int K, int lda, int ldb, int ldc)
{
    __shared__ uint32_t As2[2][16][136];   // [k2][m] half2(k, k+1) at row m
    __shared__ uint32_t Bs2[2][16][136];   // [k2][n]

    const int tid  = threadIdx.x;
    const int lane = tid & 31;
    const int warp = tid >> 5;
    const int wm = warp & 3;
    const int wn = warp >> 2;
    const int bm = blockIdx.y;
    const int n0 = blockIdx.x * 128;

    // --- A global addressing ---
    const float* aP0;      // k-row base (QKV) or m-row base (row-major)
    long aStride;          // stride between k rows (QKV) / unused
    int a_k2, a_ms;        // QKV mapping
    int a_m, a_kf;         // row-major mapping
    if (MODE == M_QKV) {
        // x element (b,c,d,t) at ((b*C+c)*2+d)*T + t ; row r=(2b+d)*T+t, k=c
        const int r0 = bm * 128;
        const int t0 = r0 & (TT - 1);
        const int bd = r0 >> 11;
        const float* Abase = A + (long)(bd >> 1) * (2L * CC * TT) + (long)(bd & 1) * TT + t0;
        a_k2 = tid >> 5;              // 0..15
        a_ms = (tid & 31) << 2;       // 0,4,...,124
        aP0  = Abase + (long)(2 * a_k2) * (2 * TT) + a_ms;
        aStride = 2 * TT;
    } else {
        a_m  = tid >> 2;              // 0..127
        a_kf = (tid & 3) << 2;        // 0,4,8,12
        aP0  = A + (long)(bm * 128 + a_m) * lda + a_kf;
        aStride = 0;
    }
    const int b_n  = tid >> 2;
    const int b_kf = (tid & 3) << 2;
    const float* bP0 = Bm + (long)(n0 + b_n) * ldb + b_kf;

    float c[2][4][4];
#pragma unroll
    for (int i = 0; i < 2; ++i)
#pragma unroll
        for (int j = 0; j < 4; ++j)
#pragma unroll
            for (int q = 0; q < 4; ++q) c[i][j][q] = 0.f;

    float4 aR0, aR1, bR0, bR1;
    // prefetch chunk 0
    if (MODE == M_QKV) {
        aR0 = *(const float4*)aP0;
        aR1 = *(const float4*)(aP0 + aStride);
    } else {
        aR0 = *(const float4*)aP0;
        aR1 = *(const float4*)(aP0 + 16);
    }
    bR0 = *(const float4*)bP0;
    bR1 = *(const float4*)(bP0 + 16);

    // stage chunk 0
    if (MODE == M_QKV) {
        As2[0][a_k2][a_ms + 0] = packh2(aR0.x, aR1.x);
        As2[0][a_k2][a_ms + 1] = packh2(aR0.y, aR1.y);
        As2[0][a_k2][a_ms + 2] = packh2(aR0.z, aR1.z);
        As2[0][a_k2][a_ms + 3] = packh2(aR0.w, aR1.w);
    } else {
        const int kr = a_kf >> 1;  // 0,2,4,6
        As2[0][kr + 0][a_m] = packh2(aR0.x, aR0.y);
        As2[0][kr + 1][a_m] = packh2(aR0.z, aR0.w);
        As2[0][kr + 8][a_m] = packh2(aR1.x, aR1.y);
        As2[0][kr + 9][a_m] = packh2(aR1.z, aR1.w);
    }
    {
        const int kr = b_kf >> 1;
        Bs2[0][kr + 0][b_n] = packh2(bR0.x, bR0.y);
        Bs2[0][kr + 1][b_n] = packh2(bR0.z, bR0.w);
        Bs2[0][kr + 8][b_n] = packh2(bR1.x, bR1.y);
        Bs2[0][kr + 9][b_n] = packh2(bR1.z, bR1.w);
    }
    __syncthreads();

    const int KT = K >> 5;
    for (int kt = 0; kt < KT; ++kt) {
        const int cur = kt & 1;
        const bool more = (kt + 1) < KT;
        if (more) {
            const long ko = (long)(kt + 1) * 32;
            if (MODE == M_QKV) {
                const float* p = aP0 + ko * (2 * TT);
                aR0 = *(const float4*)p;
                aR1 = *(const float4*)(p + aStride);
            } else {
                aR0 = *(const float4*)(aP0 + ko);
                aR1 = *(const float4*)(aP0 + ko + 16);
            }
            bR0 = *(const float4*)(bP0 + ko);
            bR1 = *(const float4*)(bP0 + ko + 16);
        }

        // compute on chunk kt
#pragma unroll
        for (int ks = 0; ks < 2; ++ks) {
            const int k2b = ks * 8;
            const int q = lane & 3;
            const int g = lane >> 2;
            uint32_t af[2][4];
            uint32_t bf[4][2];
#pragma unroll
            for (int ms = 0; ms < 2; ++ms) {
                const int m = wm * 32 + ms * 16 + g;
                af[ms][0] = As2[cur][k2b + q][m];
                af[ms][1] = As2[cur][k2b + q][m + 8];
                af[ms][2] = As2[cur][k2b + 4 + q][m];
                af[ms][3] = As2[cur][k2b + 4 + q][m + 8];
            }
#pragma unroll
            for (int ns = 0; ns < 4; ++ns) {
                const int n = wn * 32 + ns * 8 + g;
                bf[ns][0] = Bs2[cur][k2b + q][n];
                bf[ns][1] = Bs2[cur][k2b + 4 + q][n];
            }
#pragma unroll
            for (int ms = 0; ms < 2; ++ms)
#pragma unroll
                for (int ns = 0; ns < 4; ++ns)
                    mma_f16(c[ms][ns], af[ms], bf[ns]);
        }

        if (more) {
            const int nxt = cur ^ 1;
            if (MODE == M_QKV) {
                As2[nxt][a_k2][a_ms + 0] = packh2(aR0.x, aR1.x);
                As2[nxt][a_k2][a_ms + 1] = packh2(aR0.y, aR1.y);
                As2[nxt][a_k2][a_ms + 2] = packh2(aR0.z, aR1.z);
                As2[nxt][a_k2][a_ms + 3] = packh2(aR0.w, aR1.w);
            } else {
                const int kr = a_kf >> 1;
                As2[nxt][kr + 0][a_m] = packh2(aR0.x, aR0.y);
                As2[nxt][kr + 1][a_m] = packh2(aR0.z, aR0.w);
                As2[nxt][kr + 8][a_m] = packh2(aR1.x, aR1.y);
                As2[nxt][kr + 9][a_m] = packh2(aR1.z, aR1.w);
            }
            const int kr = b_kf >> 1;
            Bs2[nxt][kr + 0][b_n] = packh2(bR0.x, bR0.y);
            Bs2[nxt][kr + 1][b_n] = packh2(bR0.z, bR0.w);
            Bs2[nxt][kr + 8][b_n] = packh2(bR1.x, bR1.y);
            Bs2[nxt][kr + 9][b_n] = packh2(bR1.z, bR1.w);
        }
        __syncthreads();
    }

    // ---------------- epilogue ----------------
    const int row0 = bm * 128 + wm * 32 + (lane >> 2);
    const int col0 = n0 + wn * 32 + ((lane & 3) << 1);
#pragma unroll
    for (int ms = 0; ms < 2; ++ms) {
#pragma unroll
        for (int ns = 0; ns < 4; ++ns) {
            const int r   = row0 + ms * 16;
            const int col = col0 + ns * 8;
            const float v0 = c[ms][ns][0], v1 = c[ms][ns][1];
            const float v2 = c[ms][ns][2], v3 = c[ms][ns][3];
            if (MODE == M_FOLD) {
                *(float2*)&Cp[(long)r * ldc + col]       = make_float2(v0, v1);
                *(float2*)&Cp[(long)(r + 8) * ldc + col] = make_float2(v2, v3);
            } else if (MODE == M_QKV) {
                const int dd = (bm >> 4) & 1;
                const float bb0 = bias[dd * JJ + col];
                const float bb1 = bias[dd * JJ + col + 1];
                *(float2*)&Cp[(long)r * ldc + col]       = make_float2(v0 + bb0, v1 + bb1);
                *(float2*)&Cp[(long)(r + 8) * ldc + col] = make_float2(v2 + bb0, v3 + bb1);
            } else { // M_OUT: out[(b*C+col)*T + t]
                const int b_ = r >> 11;
                const int t_ = r & (TT - 1);
                const float bb0 = bias[col], bb1 = bias[col + 1];
                float* o0 = Cp + (long)(b_ * CC + col) * TT + t_;
                float* o1 = Cp + (long)(b_ * CC + col + 1) * TT + t_;
                o0[0] = v0 + bb0; o1[0] = v1 + bb1;
                o0[8] = v2 + bb0; o1[8] = v3 + bb1;
            }
        }
    }
}

// ---------------- attention (2x2 per head) + ctx + avg-attention ----------------
__global__ void attn_kernel()
{
    const int warp = threadIdx.x >> 5;
    const int lane = threadIdx.x & 31;
    const int n = blockIdx.x * 8 + warp;      // token
    const int b = n >> 11;
    const int t = n & (TT - 1);
    const float* row0 = g_qkv + ((long)(b * 2 + 0) * TT + t) * JJ;
    const float* row1 = g_qkv + ((long)(b * 2 + 1) * TT + t) * JJ;

    float s[4][2][2];
#pragma unroll
    for (int h = 0; h < 4; ++h) {
        float q0[4], q1[4], k0[4], k1[4];
#pragma unroll
        for (int j = 0; j < 4; ++j) {
            const int idx = h * 128 + lane + 32 * j;
            q0[j] = row0[idx];        q1[j] = row1[idx];
            k0[j] = row0[512 + idx];  k1[j] = row1[512 + idx];
        }
        float s00 = 0, s01 = 0, s10 = 0, s11 = 0;
#pragma unroll
        for (int j = 0; j < 4; ++j) {
            s00 += q0[j] * k0[j]; s01 += q0[j] * k1[j];
            s10 += q1[j] * k0[j]; s11 += q1[j] * k1[j];
        }
        s[h][0][0] = s00; s[h][0][1] = s01; s[h][1][0] = s10; s[h][1][1] = s11;
    }
#pragma unroll
    for (int h = 0; h < 4; ++h)
#pragma unroll
        for (int d = 0; d < 2; ++d)
#pragma unroll
            for (int e = 0; e < 2; ++e)
                s[h][d][e] = warp_sum(s[h][d][e]);

    const float scale = 0.0883883476483184f;  // 1/sqrt(128)
    float p[4][2][2];
#pragma unroll
    for (int h = 0; h < 4; ++h)
#pragma unroll
        for (int d = 0; d < 2; ++d) {
            const float a  = s[h][d][0] * scale;
            const float bb = s[h][d][1] * scale;
            const float mx = fmaxf(a, bb);
            const float e0 = expf(a - mx), e1 = expf(bb - mx);
            const float inv = 1.0f / (e0 + e1);
            p[h][d][0] = e0 * inv; p[h][d][1] = e1 * inv;
        }

    const float* v0 = row0 + 1024;
    const float* v1 = row1 + 1024;
    float* crow = g_ctx + (long)n * 1024;
#pragma unroll
    for (int u = 0; u < 16; ++u) {
        const int j = lane + 32 * u;
        const int h = j >> 7;
        const float a0 = v0[j], a1 = v1[j];
        crow[j]       = p[h][0][0] * a0 + p[h][0][1] * a1;
        crow[512 + j] = p[h][1][0] * a0 + p[h][1][1] * a1;
    }

    __shared__ float red[8][4];
    if (lane == 0) {
#pragma unroll
        for (int d = 0; d < 2; ++d)
#pragma unroll
            for (int e = 0; e < 2; ++e)
                red[warp][d * 2 + e] =
                    0.25f * (p[0][d][e] + p[1][d][e] + p[2][d][e] + p[3][d][e]);
    }
    __syncthreads();
    if (threadIdx.x < 4) {
        float acc = 0.f;
#pragma unroll
        for (int w = 0; w < 8; ++w) acc += red[w][threadIdx.x];
        atomicAdd(&g_att[b * 4 + threadIdx.x], acc);
    }
}

// ---------------- launch ----------------
extern "C" void kernel_launch(void* const* d_in, const int* in_sizes, int n_in,
                              void* d_out, int out_size)
{
    const float* x    = (const float*)d_in[0];
    const float* emb  = (const float*)d_in[1];
    const float* W1   = (const float*)d_in[2];
    const float* b1   = (const float*)d_in[3];
    const float* Wo   = (const float*)d_in[4];
    const float* bo   = (const float*)d_in[5];
    const float* Wp   = (const float*)d_in[6];
    const float* bp   = (const float*)d_in[7];
    const float* Wi   = (const float*)d_in[8];
    const float* bi   = (const float*)d_in[9];
    const float* Wout = (const float*)d_in[10];
    const float* bout = (const float*)d_in[11];
    float* out = (float*)d_out;

    void *p;
    float *p_WoT, *p_G0, *p_G1, *p_GT0, *p_GT1, *p_M, *p_bc, *p_qb, *p_qkv, *p_ctx;
    cudaGetSymbolAddress(&p, g_WoT); p_WoT = (float*)p;
    cudaGetSymbolAddress(&p, g_G0);  p_G0  = (float*)p;
    cudaGetSymbolAddress(&p, g_G1);  p_G1  = (float*)p;
    cudaGetSymbolAddress(&p, g_GT0); p_GT0 = (float*)p;
    cudaGetSymbolAddress(&p, g_GT1); p_GT1 = (float*)p;
    cudaGetSymbolAddress(&p, g_M);   p_M   = (float*)p;
    cudaGetSymbolAddress(&p, g_bc);  p_bc  = (float*)p;
    cudaGetSymbolAddress(&p, g_qb);  p_qb  = (float*)p;
    cudaGetSymbolAddress(&p, g_qkv); p_qkv = (float*)p;
    cudaGetSymbolAddress(&p, g_ctx); p_ctx = (float*)p;

    zero_att_kernel<<<1, 64>>>();

    // biases
    qb_kernel<<<384, 256>>>(W1, b1, emb);
    ub_kernel<<<128, 256>>>(Wp, bp, Wi, bi, bo);
    bc_kernel<<<64, 256>>>(Wout, bout);

    // fold M0 = WoutL*Wp*Wo, M1 = WoutR*Wi*Wo  (A*B^T primitive + transposes)
    transpose512<<<dim3(16, 16), dim3(32, 8)>>>(Wo, p_WoT);
    gemm_h<M_FOLD><<<dim3(4, 4), 512>>>(Wp, p_WoT, p_G0, nullptr, 512, 512, 512, 512);
    gemm_h<M_FOLD><<<dim3(4, 4), 512>>>(Wi, p_WoT, p_G1, nullptr, 512, 512, 512, 512);
    transpose512<<<dim3(16, 16), dim3(32, 8)>>>(p_G0, p_GT0);
    transpose512<<<dim3(16, 16), dim3(32, 8)>>>(p_G1, p_GT1);
    gemm_h<M_FOLD><<<dim3(4, 4), 512>>>(Wout,       p_GT0, p_M,       nullptr, 512, 1024, 512, 1024);
    gemm_h<M_FOLD><<<dim3(4, 4), 512>>>(Wout + 512, p_GT1, p_M + 512, nullptr, 512, 1024, 512, 1024);

    // QKV = x * W1^T + qb   (rows = (2b+d)*T + t)
    gemm_h<M_QKV><<<dim3(12, 512), 512>>>(x, W1, p_qkv, p_qb, 512, 0, 512, JJ);

    // attention -> ctx (N x 1024), avg-attention accumulation
    attn_kernel<<<4096, 256>>>();

    // out = ctx * Mcat^T + bc, stored transposed to (B, C, T)
    gemm_h<M_OUT><<<dim3(4, 256), 512>>>(p_ctx, p_M, out, p_bc, 1024, 1024, 1024, 0);

    // avg_attention tail (B,2,2), if present in output buffer
    if (out_size >= BB * CC * TT + BB * 4) {
        avg_out_kernel<<<1, 64>>>(out + (long)BB * CC * TT);
    }
}

// round 6
// speedup vs baseline: 1.8676x; 1.3636x over previous
#include <cuda_runtime.h>
#include <cuda_fp16.h>
#include <cstdint>
#include <math.h>

// Problem constants
#define BB 16
#define TT 2048
#define CC 512
#define NT (BB*TT)     // 32768 tokens
#define RR (NT*2)      // 65536 rows (token,device)
#define JJ 1536        // q|k|v packed

// ---------------- scratch (static device memory; no allocation) ----------------
__device__ __half g_xh[(size_t)RR * CC];      // 67 MB  x transposed+fp16: [r][c]
__device__ __half g_w1h[JJ * CC];             // 1.5 MB
__device__ __half g_qkvh[(size_t)RR * JJ];    // 201 MB
__device__ __half g_ctxh[(size_t)NT * 1024];  // 67 MB
__device__ __half g_Mh[CC * 1024];            // 1 MB
__device__ float g_WoT[CC*CC];
__device__ float g_G0[CC*CC];
__device__ float g_G1[CC*CC];
__device__ float g_GT0[CC*CC];
__device__ float g_GT1[CC*CC];
__device__ float g_M[CC*1024];
__device__ float g_bc[CC];
__device__ float g_qb[2*JJ];
__device__ float g_ucat[1024];
__device__ float g_att[BB*4];

// ---------------- helpers ----------------
__device__ __forceinline__ float warp_sum(float v) {
#pragma unroll
    for (int o = 16; o > 0; o >>= 1) v += __shfl_xor_sync(0xffffffffu, v, o);
    return v;
}
__device__ __forceinline__ uint32_t packh2(float lo, float hi) {
    __half2 h = __floats2half2_rn(lo, hi);
    return *(uint32_t*)&h;
}
__device__ __forceinline__ uint32_t smem_u32(const void* p) {
    uint32_t a;
    asm("{ .reg .u64 tmp; cvta.to.shared.u64 tmp, %1; cvt.u32.u64 %0, tmp; }"
        : "=r"(a) : "l"(p));
    return a;
}
__device__ __forceinline__ void cp16(uint32_t dst, const void* src) {
    asm volatile("cp.async.cg.shared.global [%0], [%1], 16;" :: "r"(dst), "l"(src));
}
__device__ __forceinline__ void mma_f16(float* c, const uint32_t* a, const uint32_t* b) {
    asm volatile(
        "mma.sync.aligned.m16n8k16.row.col.f32.f16.f16.f32 "
        "{%0,%1,%2,%3}, {%4,%5,%6,%7}, {%8,%9}, {%0,%1,%2,%3};\n"
        : "+f"(c[0]), "+f"(c[1]), "+f"(c[2]), "+f"(c[3])
        : "r"(a[0]), "r"(a[1]), "r"(a[2]), "r"(a[3]), "r"(b[0]), "r"(b[1]));
}

// ---------------- small prep kernels ----------------
__global__ void zero_att_kernel() {
    if (threadIdx.x < BB*4) g_att[threadIdx.x] = 0.f;
}

__global__ void qb_kernel(const float* __restrict__ W1, const float* __restrict__ b1,
                          const float* __restrict__ emb) {
    int widx = (blockIdx.x * blockDim.x + threadIdx.x) >> 5;
    int lane = threadIdx.x & 31;
    if (widx >= 2 * JJ) return;
    int d = widx / JJ, j = widx % JJ;
    const float* wrow = W1 + (long)j * CC;
    const float* e = emb + d * CC;
    float s = 0.f;
    for (int c = lane; c < CC; c += 32) s += wrow[c] * e[c];
    s = warp_sum(s);
    if (lane == 0) g_qb[widx] = b1[j] + s;
}

__global__ void ub_kernel(const float* __restrict__ Wp, const float* __restrict__ bp,
                          const float* __restrict__ Wi, const float* __restrict__ bi,
                          const float* __restrict__ bo) {
    int widx = (blockIdx.x * blockDim.x + threadIdx.x) >> 5;
    int lane = threadIdx.x & 31;
    if (widx >= 1024) return;
    const float* wrow;
    float bias;
    if (widx < CC) { wrow = Wp + (long)widx * CC; bias = bp[widx]; }
    else           { wrow = Wi + (long)(widx - CC) * CC; bias = bi[widx - CC]; }
    float s = 0.f;
    for (int c = lane; c < CC; c += 32) s += wrow[c] * bo[c];
    s = warp_sum(s);
    if (lane == 0) g_ucat[widx] = bias + s;
}

__global__ void bc_kernel(const float* __restrict__ Wout, const float* __restrict__ bout) {
    int widx = (blockIdx.x * blockDim.x + threadIdx.x) >> 5;
    int lane = threadIdx.x & 31;
    if (widx >= CC) return;
    const float* wrow = Wout + (long)widx * 1024;
    float s = 0.f;
    for (int c = lane; c < 1024; c += 32) s += wrow[c] * g_ucat[c];
    s = warp_sum(s);
    if (lane == 0) g_bc[widx] = bout[widx] + s;
}

__global__ void transpose512(const float* __restrict__ src, float* __restrict__ dst) {
    __shared__ float tile[32][33];
    int x = blockIdx.x * 32 + threadIdx.x;
    int y = blockIdx.y * 32 + threadIdx.y;
#pragma unroll
    for (int i = 0; i < 32; i += 8)
        tile[threadIdx.y + i][threadIdx.x] = src[(long)(y + i) * 512 + x];
    __syncthreads();
    x = blockIdx.y * 32 + threadIdx.x;
    y = blockIdx.x * 32 + threadIdx.y;
#pragma unroll
    for (int i = 0; i < 32; i += 8)
        dst[(long)(y + i) * 512 + x] = tile[threadIdx.x][threadIdx.y + i];
}

// x (B,C,2,T) fp32 -> xh[(2b+d)*T + t][c] fp16  (per-(b,d) [C][T] -> [T][C] transpose)
__global__ void xpose_kernel(const float* __restrict__ x) {
    __shared__ float tile[32][33];
    const int bd = blockIdx.z;           // 0..31 = b*2+d
    const int b = bd >> 1, d = bd & 1;
    const float* src = x + ((long)b * CC * 2 + d) * TT;  // element (c,t) at c*(2T) + t
    int t = blockIdx.x * 32 + threadIdx.x;
    int c = blockIdx.y * 32 + threadIdx.y;
#pragma unroll
    for (int i = 0; i < 32; i += 8)
        tile[threadIdx.y + i][threadIdx.x] = src[(long)(c + i) * (2 * TT) + t];
    __syncthreads();
    int tw = blockIdx.x * 32 + threadIdx.y;
    int cw = blockIdx.y * 32 + threadIdx.x;
    __half* dst = g_xh + ((long)bd * TT) * CC;
#pragma unroll
    for (int i = 0; i < 32; i += 8)
        dst[(long)(tw + i) * CC + cw] = __float2half_rn(tile[threadIdx.x][threadIdx.y + i]);
}

// fp32 -> fp16 elementwise (n multiple of 4)
__global__ void f2h_kernel(const float* __restrict__ s, __half* __restrict__ d, long n) {
    long i = ((long)blockIdx.x * blockDim.x + threadIdx.x) * 4;
    if (i < n) {
        float4 v = *(const float4*)(s + i);
        *(__half2*)(d + i)     = __floats2half2_rn(v.x, v.y);
        *(__half2*)(d + i + 2) = __floats2half2_rn(v.z, v.w);
    }
}

__global__ void avg_out_kernel(float* __restrict__ dst) {
    if (threadIdx.x < BB*4) dst[threadIdx.x] = g_att[threadIdx.x] * (1.0f / (float)TT);
}

// ---------------- fold GEMM (fp32 in, fp16 mma) — proven R5 path, FOLD only ----------------
__global__ __launch_bounds__(512)
void gemm_fold(const float* __restrict__ A, const float* __restrict__ Bm,
               float* __restrict__ Cp, int K, int lda, int ldb, int ldc)
{
    __shared__ uint32_t As2[2][16][136];
    __shared__ uint32_t Bs2[2][16][136];
    const int tid  = threadIdx.x;
    const int lane = tid & 31;
    const int warp = tid >> 5;
    const int wm = warp & 3, wn = warp >> 2;
    const int bm = blockIdx.y, n0 = blockIdx.x * 128;

    const int a_m  = tid >> 2, a_kf = (tid & 3) << 2;
    const float* aP0 = A + (long)(bm * 128 + a_m) * lda + a_kf;
    const int b_n  = tid >> 2, b_kf = (tid & 3) << 2;
    const float* bP0 = Bm + (long)(n0 + b_n) * ldb + b_kf;

    float c[2][4][4];
#pragma unroll
    for (int i = 0; i < 2; ++i)
#pragma unroll
        for (int j = 0; j < 4; ++j)
#pragma unroll
            for (int q = 0; q < 4; ++q) c[i][j][q] = 0.f;

    float4 aR0 = *(const float4*)aP0;
    float4 aR1 = *(const float4*)(aP0 + 16);
    float4 bR0 = *(const float4*)bP0;
    float4 bR1 = *(const float4*)(bP0 + 16);
    {
        const int kr = a_kf >> 1;
        As2[0][kr + 0][a_m] = packh2(aR0.x, aR0.y);
        As2[0][kr + 1][a_m] = packh2(aR0.z, aR0.w);
        As2[0][kr + 8][a_m] = packh2(aR1.x, aR1.y);
        As2[0][kr + 9][a_m] = packh2(aR1.z, aR1.w);
        const int krb = b_kf >> 1;
        Bs2[0][krb + 0][b_n] = packh2(bR0.x, bR0.y);
        Bs2[0][krb + 1][b_n] = packh2(bR0.z, bR0.w);
        Bs2[0][krb + 8][b_n] = packh2(bR1.x, bR1.y);
        Bs2[0][krb + 9][b_n] = packh2(bR1.z, bR1.w);
    }
    __syncthreads();

    const int KT = K >> 5;
    for (int kt = 0; kt < KT; ++kt) {
        const int cur = kt & 1;
        const bool more = (kt + 1) < KT;
        if (more) {
            const long ko = (long)(kt + 1) * 32;
            aR0 = *(const float4*)(aP0 + ko);
            aR1 = *(const float4*)(aP0 + ko + 16);
            bR0 = *(const float4*)(bP0 + ko);
            bR1 = *(const float4*)(bP0 + ko + 16);
        }
#pragma unroll
        for (int ks = 0; ks < 2; ++ks) {
            const int k2b = ks * 8;
            const int q = lane & 3, g = lane >> 2;
            uint32_t af[2][4], bf[4][2];
#pragma unroll
            for (int ms = 0; ms < 2; ++ms) {
                const int m = wm * 32 + ms * 16 + g;
                af[ms][0] = As2[cur][k2b + q][m];
                af[ms][1] = As2[cur][k2b + q][m + 8];
                af[ms][2] = As2[cur][k2b + 4 + q][m];
                af[ms][3] = As2[cur][k2b + 4 + q][m + 8];
            }
#pragma unroll
            for (int ns = 0; ns < 4; ++ns) {
                const int n = wn * 32 + ns * 8 + g;
                bf[ns][0] = Bs2[cur][k2b + q][n];
                bf[ns][1] = Bs2[cur][k2b + 4 + q][n];
            }
#pragma unroll
            for (int ms = 0; ms < 2; ++ms)
#pragma unroll
                for (int ns = 0; ns < 4; ++ns)
                    mma_f16(c[ms][ns], af[ms], bf[ns]);
        }
        if (more) {
            const int nxt = cur ^ 1;
            const int kr = a_kf >> 1;
            As2[nxt][kr + 0][a_m] = packh2(aR0.x, aR0.y);
            As2[nxt][kr + 1][a_m] = packh2(aR0.z, aR0.w);
            As2[nxt][kr + 8][a_m] = packh2(aR1.x, aR1.y);
            As2[nxt][kr + 9][a_m] = packh2(aR1.z, aR1.w);
            const int krb = b_kf >> 1;
            Bs2[nxt][krb + 0][b_n] = packh2(bR0.x, bR0.y);
            Bs2[nxt][krb + 1][b_n] = packh2(bR0.z, bR0.w);
            Bs2[nxt][krb + 8][b_n] = packh2(bR1.x, bR1.y);
            Bs2[nxt][krb + 9][b_n] = packh2(bR1.z, bR1.w);
        }
        __syncthreads();
    }

    const int row0 = bm * 128 + wm * 32 + (lane >> 2);
    const int col0 = n0 + wn * 32 + ((lane & 3) << 1);
#pragma unroll
    for (int ms = 0; ms < 2; ++ms)
#pragma unroll
        for (int ns = 0; ns < 4; ++ns) {
            const int r   = row0 + ms * 16;
            const int col = col0 + ns * 8;
            *(float2*)&Cp[(long)r * ldc + col]       = make_float2(c[ms][ns][0], c[ms][ns][1]);
            *(float2*)&Cp[(long)(r + 8) * ldc + col] = make_float2(c[ms][ns][2], c[ms][ns][3]);
        }
}

// ---------------- pipelined fp16 GEMM: C = A * B^T (cp.async 4-stage) ----------------
// A, B fp16 row-major k-contiguous. BM=BN=128, BK=32, 512 threads, warp tile 32x32.
// Smem per stage: A 128 rows x 20 words (16 data + 4 pad), B same. Stride-20 rows
// make all fragment LDS patterns bank-conflict-free (banks 20g+q+c distinct mod 32).
// One commit_group per chunk (empty groups near the tail) => wait_group 2 exact.
enum { P_QKV = 0, P_OUT = 1 };

#define S_STAGES 4
#define RW 20
#define A_STG_BYTES (128*RW*4)      // 10240
#define STG_BYTES   (2*A_STG_BYTES) // 20480
#define GA_SMEM (S_STAGES*STG_BYTES) // 81920

template<int MODE>
__global__ __launch_bounds__(512)
void gemm_a(const __half* __restrict__ A, const __half* __restrict__ Bm,
            void* __restrict__ Cp, const float* __restrict__ bias,
            int K, int lda, int ldb)
{
    extern __shared__ char smem[];
    const uint32_t sbase = smem_u32(smem);
    const int tid = threadIdx.x, lane = tid & 31, warp = tid >> 5;
    const int wm = warp & 3, wn = warp >> 2;
    const int bm = blockIdx.y, n0 = blockIdx.x * 128;

    const int srow = tid >> 2, sch = tid & 3;
    const __half* aSrc = A + (long)(bm * 128 + srow) * lda + sch * 8;
    const __half* bSrc = Bm + (long)(n0 + srow) * ldb + sch * 8;
    const uint32_t dstOff = srow * (RW * 4) + sch * 16;

    const int KT = K >> 5;
    // preload stages 0..2
#pragma unroll
    for (int s = 0; s < S_STAGES - 1; ++s) {
        if (s < KT) {
            cp16(sbase + s * STG_BYTES + dstOff, aSrc + s * 32);
            cp16(sbase + s * STG_BYTES + A_STG_BYTES + dstOff, bSrc + s * 32);
        }
        asm volatile("cp.async.commit_group;" ::: "memory");
    }

    float c[2][4][4];
#pragma unroll
    for (int i = 0; i < 2; ++i)
#pragma unroll
        for (int j = 0; j < 4; ++j)
#pragma unroll
            for (int q = 0; q < 4; ++q) c[i][j][q] = 0.f;

    for (int kt = 0; kt < KT; ++kt) {
        asm volatile("cp.async.wait_group 2;" ::: "memory");
        __syncthreads();
        // issue stage kt+3 into buffer (kt+3)&3 (freed by the sync above)
        {
            const int s = kt + S_STAGES - 1;
            if (s < KT) {
                const int buf = s & (S_STAGES - 1);
                cp16(sbase + buf * STG_BYTES + dstOff, aSrc + (long)s * 32);
                cp16(sbase + buf * STG_BYTES + A_STG_BYTES + dstOff, bSrc + (long)s * 32);
            }
            asm volatile("cp.async.commit_group;" ::: "memory");
        }
        // compute chunk kt from buffer kt&3
        const uint32_t* As = (const uint32_t*)(smem + (kt & 3) * STG_BYTES);
        const uint32_t* Bs = (const uint32_t*)(smem + (kt & 3) * STG_BYTES + A_STG_BYTES);
        const int q = lane & 3, g = lane >> 2;
#pragma unroll
        for (int ks = 0; ks < 2; ++ks) {
            const int kb = ks * 8;
            uint32_t af[2][4], bf[4][2];
#pragma unroll
            for (int ms = 0; ms < 2; ++ms) {
                const int m = wm * 32 + ms * 16 + g;
                af[ms][0] = As[m * RW + kb + q];
                af[ms][1] = As[(m + 8) * RW + kb + q];
                af[ms][2] = As[m * RW + kb + q + 4];
                af[ms][3] = As[(m + 8) * RW + kb + q + 4];
            }
#pragma unroll
            for (int ns = 0; ns < 4; ++ns) {
                const int n = wn * 32 + ns * 8 + g;
                bf[ns][0] = Bs[n * RW + kb + q];
                bf[ns][1] = Bs[n * RW + kb + q + 4];
            }
#pragma unroll
            for (int ms = 0; ms < 2; ++ms)
#pragma unroll
                for (int ns = 0; ns < 4; ++ns)
                    mma_f16(c[ms][ns], af[ms], bf[ns]);
        }
    }

    // epilogue
    const int row0 = bm * 128 + wm * 32 + (lane >> 2);
    const int col0 = n0 + wn * 32 + ((lane & 3) << 1);
#pragma unroll
    for (int ms = 0; ms < 2; ++ms)
#pragma unroll
        for (int ns = 0; ns < 4; ++ns) {
            const int r   = row0 + ms * 16;
            const int col = col0 + ns * 8;
            const float v0 = c[ms][ns][0], v1 = c[ms][ns][1];
            const float v2 = c[ms][ns][2], v3 = c[ms][ns][3];
            if (MODE == P_QKV) {
                const int dd = (bm >> 4) & 1;
                const float bb0 = bias[dd * JJ + col];
                const float bb1 = bias[dd * JJ + col + 1];
                __half2* O = (__half2*)Cp;
                O[((long)r * JJ + col) >> 1]       = __floats2half2_rn(v0 + bb0, v1 + bb1);
                O[((long)(r + 8) * JJ + col) >> 1] = __floats2half2_rn(v2 + bb0, v3 + bb1);
            } else {  // P_OUT: out[(b*C+col)*T + t]
                float* Of = (float*)Cp;
                const int b_ = r >> 11;
                const int t_ = r & (TT - 1);
                const float bb0 = bias[col], bb1 = bias[col + 1];
                float* o0 = Of + (long)(b_ * CC + col) * TT + t_;
                float* o1 = Of + (long)(b_ * CC + col + 1) * TT + t_;
                o0[0] = v0 + bb0; o1[0] = v1 + bb1;
                o0[8] = v2 + bb0; o1[8] = v3 + bb1;
            }
        }
}

// ---------------- attention (fp16 qkv -> fp16 ctx) ----------------
__global__ void attn_kernel()
{
    const int warp = threadIdx.x >> 5;
    const int lane = threadIdx.x & 31;
    const int n = blockIdx.x * 8 + warp;      // token
    const int b = n >> 11;
    const int t = n & (TT - 1);
    const __half2* r0 = (const __half2*)(g_qkvh + ((long)(b * 2 + 0) * TT + t) * JJ);
    const __half2* r1 = (const __half2*)(g_qkvh + ((long)(b * 2 + 1) * TT + t) * JJ);

    float s[4][2][2];
#pragma unroll
    for (int h = 0; h < 4; ++h) {
        float s00 = 0, s01 = 0, s10 = 0, s11 = 0;
#pragma unroll
        for (int j = 0; j < 2; ++j) {
            const int i2 = h * 64 + lane + 32 * j;
            const float2 q0 = __half22float2(r0[i2]);
            const float2 q1 = __half22float2(r1[i2]);
            const float2 k0 = __half22float2(r0[256 + i2]);
            const float2 k1 = __half22float2(r1[256 + i2]);
            s00 += q0.x * k0.x + q0.y * k0.y;
            s01 += q0.x * k1.x + q0.y * k1.y;
            s10 += q1.x * k0.x + q1.y * k0.y;
            s11 += q1.x * k1.x + q1.y * k1.y;
        }
        s[h][0][0] = s00; s[h][0][1] = s01; s[h][1][0] = s10; s[h][1][1] = s11;
    }
#pragma unroll
    for (int h = 0; h < 4; ++h)
#pragma unroll
        for (int d = 0; d < 2; ++d)
#pragma unroll
            for (int e = 0; e < 2; ++e)
                s[h][d][e] = warp_sum(s[h][d][e]);

    const float scale = 0.0883883476483184f;  // 1/sqrt(128)
    float p[4][2][2];
#pragma unroll
    for (int h = 0; h < 4; ++h)
#pragma unroll
        for (int d = 0; d < 2; ++d) {
            const float a  = s[h][d][0] * scale;
            const float bb = s[h][d][1] * scale;
            const float mx = fmaxf(a, bb);
            const float e0 = expf(a - mx), e1 = expf(bb - mx);
            const float inv = 1.0f / (e0 + e1);
            p[h][d][0] = e0 * inv; p[h][d][1] = e1 * inv;
        }

    __half2* crow = (__half2*)(g_ctxh + (long)n * 1024);
#pragma unroll
    for (int u = 0; u < 8; ++u) {
        const int j2 = lane + 32 * u;          // half2 index 0..255 within device slot
        const int h = j2 >> 6;
        const float2 a0 = __half22float2(r0[512 + j2]);
        const float2 a1 = __half22float2(r1[512 + j2]);
        crow[j2] = __floats2half2_rn(p[h][0][0] * a0.x + p[h][0][1] * a1.x,
                                     p[h][0][0] * a0.y + p[h][0][1] * a1.y);
        crow[256 + j2] = __floats2half2_rn(p[h][1][0] * a0.x + p[h][1][1] * a1.x,
                                           p[h][1][0] * a0.y + p[h][1][1] * a1.y);
    }

    __shared__ float red[8][4];
    if (lane == 0) {
#pragma unroll
        for (int d = 0; d < 2; ++d)
#pragma unroll
            for (int e = 0; e < 2; ++e)
                red[warp][d * 2 + e] =
                    0.25f * (p[0][d][e] + p[1][d][e] + p[2][d][e] + p[3][d][e]);
    }
    __syncthreads();
    if (threadIdx.x < 4) {
        float acc = 0.f;
#pragma unroll
        for (int w = 0; w < 8; ++w) acc += red[w][threadIdx.x];
        atomicAdd(&g_att[b * 4 + threadIdx.x], acc);
    }
}

// ---------------- launch ----------------
extern "C" void kernel_launch(void* const* d_in, const int* in_sizes, int n_in,
                              void* d_out, int out_size)
{
    const float* x    = (const float*)d_in[0];
    const float* emb  = (const float*)d_in[1];
    const float* W1   = (const float*)d_in[2];
    const float* b1   = (const float*)d_in[3];
    const float* Wo   = (const float*)d_in[4];
    const float* bo   = (const float*)d_in[5];
    const float* Wp   = (const float*)d_in[6];
    const float* bp   = (const float*)d_in[7];
    const float* Wi   = (const float*)d_in[8];
    const float* bi   = (const float*)d_in[9];
    const float* Wout = (const float*)d_in[10];
    const float* bout = (const float*)d_in[11];
    float* out = (float*)d_out;

    void *p;
    float *p_WoT, *p_G0, *p_G1, *p_GT0, *p_GT1, *p_M, *p_bc, *p_qb;
    __half *p_xh, *p_w1h, *p_qkvh, *p_ctxh, *p_Mh;
    cudaGetSymbolAddress(&p, g_WoT);  p_WoT  = (float*)p;
    cudaGetSymbolAddress(&p, g_G0);   p_G0   = (float*)p;
    cudaGetSymbolAddress(&p, g_G1);   p_G1   = (float*)p;
    cudaGetSymbolAddress(&p, g_GT0);  p_GT0  = (float*)p;
    cudaGetSymbolAddress(&p, g_GT1);  p_GT1  = (float*)p;
    cudaGetSymbolAddress(&p, g_M);    p_M    = (float*)p;
    cudaGetSymbolAddress(&p, g_bc);   p_bc   = (float*)p;
    cudaGetSymbolAddress(&p, g_qb);   p_qb   = (float*)p;
    cudaGetSymbolAddress(&p, g_xh);   p_xh   = (__half*)p;
    cudaGetSymbolAddress(&p, g_w1h);  p_w1h  = (__half*)p;
    cudaGetSymbolAddress(&p, g_qkvh); p_qkvh = (__half*)p;
    cudaGetSymbolAddress(&p, g_ctxh); p_ctxh = (__half*)p;
    cudaGetSymbolAddress(&p, g_Mh);   p_Mh   = (__half*)p;

    cudaFuncSetAttribute(gemm_a<P_QKV>, cudaFuncAttributeMaxDynamicSharedMemorySize, GA_SMEM);
    cudaFuncSetAttribute(gemm_a<P_OUT>, cudaFuncAttributeMaxDynamicSharedMemorySize, GA_SMEM);

    zero_att_kernel<<<1, 64>>>();

    // biases (fp32 weights)
    qb_kernel<<<384, 256>>>(W1, b1, emb);
    ub_kernel<<<128, 256>>>(Wp, bp, Wi, bi, bo);
    bc_kernel<<<64, 256>>>(Wout, bout);

    // fp16 operand prep
    xpose_kernel<<<dim3(64, 16, 32), dim3(32, 8)>>>(x);
    f2h_kernel<<<(JJ * CC / 4 + 255) / 256, 256>>>(W1, p_w1h, (long)JJ * CC);

    // fold M0 = WoutL*Wp*Wo, M1 = WoutR*Wi*Wo
    transpose512<<<dim3(16, 16), dim3(32, 8)>>>(Wo, p_WoT);
    gemm_fold<<<dim3(4, 4), 512>>>(Wp, p_WoT, p_G0, 512, 512, 512, 512);
    gemm_fold<<<dim3(4, 4), 512>>>(Wi, p_WoT, p_G1, 512, 512, 512, 512);
    transpose512<<<dim3(16, 16), dim3(32, 8)>>>(p_G0, p_GT0);
    transpose512<<<dim3(16, 16), dim3(32, 8)>>>(p_G1, p_GT1);
    gemm_fold<<<dim3(4, 4), 512>>>(Wout,       p_GT0, p_M,       512, 1024, 512, 1024);
    gemm_fold<<<dim3(4, 4), 512>>>(Wout + 512, p_GT1, p_M + 512, 512, 1024, 512, 1024);
    f2h_kernel<<<(CC * 1024 / 4 + 255) / 256, 256>>>(p_M, p_Mh, (long)CC * 1024);

    // QKV = xh * W1h^T + qb  -> fp16 qkv
    gemm_a<P_QKV><<<dim3(12, 512), 512, GA_SMEM>>>(p_xh, p_w1h, p_qkvh, p_qb, 512, 512, 512);

    // attention -> fp16 ctx
    attn_kernel<<<4096, 256>>>();

    // out = ctxh * Mh^T + bc, stored transposed to (B, C, T) fp32
    gemm_a<P_OUT><<<dim3(4, 256), 512, GA_SMEM>>>(p_ctxh, p_Mh, out, p_bc, 1024, 1024, 1024);

    if (out_size >= BB * CC * TT + BB * 4) {
        avg_out_kernel<<<1, 64>>>(out + (long)BB * CC * TT);
    }
}

// round 8
// speedup vs baseline: 2.1455x; 1.1488x over previous
#include <cuda_runtime.h>
#include <cuda_fp16.h>
#include <cstdint>
#include <math.h>

// Problem constants
#define BB 16
#define TT 2048
#define CC 512
#define NT (BB*TT)     // 32768 tokens
#define RR (NT*2)      // 65536 rows (token,device)
#define JJ 1536        // q|k|v packed

// ---------------- scratch (static device memory; no allocation) ----------------
__device__ __half g_xh[(size_t)RR * CC];      // 67 MB  x transposed+fp16: [r][c]
__device__ __half g_w1h[JJ * CC];             // 1.5 MB
__device__ __half g_qkvh[(size_t)RR * JJ];    // 201 MB
__device__ __half g_ctxh[(size_t)NT * 1024];  // 67 MB
__device__ __half g_Mh[CC * 1024];            // 1 MB
__device__ float g_WoT[CC*CC];
__device__ float g_G0[CC*CC];
__device__ float g_G1[CC*CC];
__device__ float g_GT0[CC*CC];
__device__ float g_GT1[CC*CC];
__device__ float g_M[CC*1024];
__device__ float g_bc[CC];
__device__ float g_qb[2*JJ];
__device__ float g_ucat[1024];
__device__ float g_att[BB*4];

// ---------------- helpers ----------------
__device__ __forceinline__ float warp_sum(float v) {
#pragma unroll
    for (int o = 16; o > 0; o >>= 1) v += __shfl_xor_sync(0xffffffffu, v, o);
    return v;
}
__device__ __forceinline__ uint32_t packh2(float lo, float hi) {
    __half2 h = __floats2half2_rn(lo, hi);
    return *(uint32_t*)&h;
}
__device__ __forceinline__ uint32_t smem_u32(const void* p) {
    uint32_t a;
    asm("{ .reg .u64 tmp; cvta.to.shared.u64 tmp, %1; cvt.u32.u64 %0, tmp; }"
        : "=r"(a) : "l"(p));
    return a;
}
__device__ __forceinline__ void cp16(uint32_t dst, const void* src) {
    asm volatile("cp.async.cg.shared.global [%0], [%1], 16;" :: "r"(dst), "l"(src));
}
__device__ __forceinline__ void mma_f16(float* c, const uint32_t* a, const uint32_t* b) {
    asm volatile(
        "mma.sync.aligned.m16n8k16.row.col.f32.f16.f16.f32 "
        "{%0,%1,%2,%3}, {%4,%5,%6,%7}, {%8,%9}, {%0,%1,%2,%3};\n"
        : "+f"(c[0]), "+f"(c[1]), "+f"(c[2]), "+f"(c[3])
        : "r"(a[0]), "r"(a[1]), "r"(a[2]), "r"(a[3]), "r"(b[0]), "r"(b[1]));
}
__device__ __forceinline__ void ldsm4(uint32_t& r0, uint32_t& r1, uint32_t& r2,
                                      uint32_t& r3, uint32_t addr) {
    asm volatile("ldmatrix.sync.aligned.m8n8.x4.shared.b16 {%0,%1,%2,%3}, [%4];"
        : "=r"(r0), "=r"(r1), "=r"(r2), "=r"(r3) : "r"(addr));
}

// ---------------- small prep kernels ----------------
__global__ void zero_att_kernel() {
    if (threadIdx.x < BB*4) g_att[threadIdx.x] = 0.f;
}

__global__ void qb_kernel(const float* __restrict__ W1, const float* __restrict__ b1,
                          const float* __restrict__ emb) {
    int widx = (blockIdx.x * blockDim.x + threadIdx.x) >> 5;
    int lane = threadIdx.x & 31;
    if (widx >= 2 * JJ) return;
    int d = widx / JJ, j = widx % JJ;
    const float* wrow = W1 + (long)j * CC;
    const float* e = emb + d * CC;
    float s = 0.f;
    for (int c = lane; c < CC; c += 32) s += wrow[c] * e[c];
    s = warp_sum(s);
    if (lane == 0) g_qb[widx] = b1[j] + s;
}

__global__ void ub_kernel(const float* __restrict__ Wp, const float* __restrict__ bp,
                          const float* __restrict__ Wi, const float* __restrict__ bi,
                          const float* __restrict__ bo) {
    int widx = (blockIdx.x * blockDim.x + threadIdx.x) >> 5;
    int lane = threadIdx.x & 31;
    if (widx >= 1024) return;
    const float* wrow;
    float bias;
    if (widx < CC) { wrow = Wp + (long)widx * CC; bias = bp[widx]; }
    else           { wrow = Wi + (long)(widx - CC) * CC; bias = bi[widx - CC]; }
    float s = 0.f;
    for (int c = lane; c < CC; c += 32) s += wrow[c] * bo[c];
    s = warp_sum(s);
    if (lane == 0) g_ucat[widx] = bias + s;
}

__global__ void bc_kernel(const float* __restrict__ Wout, const float* __restrict__ bout) {
    int widx = (blockIdx.x * blockDim.x + threadIdx.x) >> 5;
    int lane = threadIdx.x & 31;
    if (widx >= CC) return;
    const float* wrow = Wout + (long)widx * 1024;
    float s = 0.f;
    for (int c = lane; c < 1024; c += 32) s += wrow[c] * g_ucat[c];
    s = warp_sum(s);
    if (lane == 0) g_bc[widx] = bout[widx] + s;
}

__global__ void transpose512(const float* __restrict__ src, float* __restrict__ dst) {
    __shared__ float tile[32][33];
    int x = blockIdx.x * 32 + threadIdx.x;
    int y = blockIdx.y * 32 + threadIdx.y;
#pragma unroll
    for (int i = 0; i < 32; i += 8)
        tile[threadIdx.y + i][threadIdx.x] = src[(long)(y + i) * 512 + x];
    __syncthreads();
    x = blockIdx.y * 32 + threadIdx.x;
    y = blockIdx.x * 32 + threadIdx.y;
#pragma unroll
    for (int i = 0; i < 32; i += 8)
        dst[(long)(y + i) * 512 + x] = tile[threadIdx.x][threadIdx.y + i];
}

// x (B,C,2,T) fp32 -> xh[(2b+d)*T + t][c] fp16
__global__ void xpose_kernel(const float* __restrict__ x) {
    __shared__ float tile[32][33];
    const int bd = blockIdx.z;           // 0..31 = b*2+d
    const int b = bd >> 1, d = bd & 1;
    const float* src = x + ((long)b * CC * 2 + d) * TT;
    int t = blockIdx.x * 32 + threadIdx.x;
    int c = blockIdx.y * 32 + threadIdx.y;
#pragma unroll
    for (int i = 0; i < 32; i += 8)
        tile[threadIdx.y + i][threadIdx.x] = src[(long)(c + i) * (2 * TT) + t];
    __syncthreads();
    int tw = blockIdx.x * 32 + threadIdx.y;
    int cw = blockIdx.y * 32 + threadIdx.x;
    __half* dst = g_xh + ((long)bd * TT) * CC;
#pragma unroll
    for (int i = 0; i < 32; i += 8)
        dst[(long)(tw + i) * CC + cw] = __float2half_rn(tile[threadIdx.x][threadIdx.y + i]);
}

__global__ void f2h_kernel(const float* __restrict__ s, __half* __restrict__ d, long n) {
    long i = ((long)blockIdx.x * blockDim.x + threadIdx.x) * 4;
    if (i < n) {
        float4 v = *(const float4*)(s + i);
        *(__half2*)(d + i)     = __floats2half2_rn(v.x, v.y);
        *(__half2*)(d + i + 2) = __floats2half2_rn(v.z, v.w);
    }
}

__global__ void avg_out_kernel(float* __restrict__ dst) {
    if (threadIdx.x < BB*4) dst[threadIdx.x] = g_att[threadIdx.x] * (1.0f / (float)TT);
}

// ---------------- fold GEMM (fp32 in, fp16 mma) — proven R5 path ----------------
__global__ __launch_bounds__(512)
void gemm_fold(const float* __restrict__ A, const float* __restrict__ Bm,
               float* __restrict__ Cp, int K, int lda, int ldb, int ldc)
{
    __shared__ uint32_t As2[2][16][136];
    __shared__ uint32_t Bs2[2][16][136];
    const int tid  = threadIdx.x;
    const int lane = tid & 31;
    const int warp = tid >> 5;
    const int wm = warp & 3, wn = warp >> 2;
    const int bm = blockIdx.y, n0 = blockIdx.x * 128;

    const int a_m  = tid >> 2, a_kf = (tid & 3) << 2;
    const float* aP0 = A + (long)(bm * 128 + a_m) * lda + a_kf;
    const int b_n  = tid >> 2, b_kf = (tid & 3) << 2;
    const float* bP0 = Bm + (long)(n0 + b_n) * ldb + b_kf;

    float c[2][4][4];
#pragma unroll
    for (int i = 0; i < 2; ++i)
#pragma unroll
        for (int j = 0; j < 4; ++j)
#pragma unroll
            for (int q = 0; q < 4; ++q) c[i][j][q] = 0.f;

    float4 aR0 = *(const float4*)aP0;
    float4 aR1 = *(const float4*)(aP0 + 16);
    float4 bR0 = *(const float4*)bP0;
    float4 bR1 = *(const float4*)(bP0 + 16);
    {
        const int kr = a_kf >> 1;
        As2[0][kr + 0][a_m] = packh2(aR0.x, aR0.y);
        As2[0][kr + 1][a_m] = packh2(aR0.z, aR0.w);
        As2[0][kr + 8][a_m] = packh2(aR1.x, aR1.y);
        As2[0][kr + 9][a_m] = packh2(aR1.z, aR1.w);
        const int krb = b_kf >> 1;
        Bs2[0][krb + 0][b_n] = packh2(bR0.x, bR0.y);
        Bs2[0][krb + 1][b_n] = packh2(bR0.z, bR0.w);
        Bs2[0][krb + 8][b_n] = packh2(bR1.x, bR1.y);
        Bs2[0][krb + 9][b_n] = packh2(bR1.z, bR1.w);
    }
    __syncthreads();

    const int KT = K >> 5;
    for (int kt = 0; kt < KT; ++kt) {
        const int cur = kt & 1;
        const bool more = (kt + 1) < KT;
        if (more) {
            const long ko = (long)(kt + 1) * 32;
            aR0 = *(const float4*)(aP0 + ko);
            aR1 = *(const float4*)(aP0 + ko + 16);
            bR0 = *(const float4*)(bP0 + ko);
            bR1 = *(const float4*)(bP0 + ko + 16);
        }
#pragma unroll
        for (int ks = 0; ks < 2; ++ks) {
            const int k2b = ks * 8;
            const int q = lane & 3, g = lane >> 2;
            uint32_t af[2][4], bf[4][2];
#pragma unroll
            for (int ms = 0; ms < 2; ++ms) {
                const int m = wm * 32 + ms * 16 + g;
                af[ms][0] = As2[cur][k2b + q][m];
                af[ms][1] = As2[cur][k2b + q][m + 8];
                af[ms][2] = As2[cur][k2b + 4 + q][m];
                af[ms][3] = As2[cur][k2b + 4 + q][m + 8];
            }
#pragma unroll
            for (int ns = 0; ns < 4; ++ns) {
                const int n = wn * 32 + ns * 8 + g;
                bf[ns][0] = Bs2[cur][k2b + q][n];
                bf[ns][1] = Bs2[cur][k2b + 4 + q][n];
            }
#pragma unroll
            for (int ms = 0; ms < 2; ++ms)
#pragma unroll
                for (int ns = 0; ns < 4; ++ns)
                    mma_f16(c[ms][ns], af[ms], bf[ns]);
        }
        if (more) {
            const int nxt = cur ^ 1;
            const int kr = a_kf >> 1;
            As2[nxt][kr + 0][a_m] = packh2(aR0.x, aR0.y);
            As2[nxt][kr + 1][a_m] = packh2(aR0.z, aR0.w);
            As2[nxt][kr + 8][a_m] = packh2(aR1.x, aR1.y);
            As2[nxt][kr + 9][a_m] = packh2(aR1.z, aR1.w);
            const int krb = b_kf >> 1;
            Bs2[nxt][krb + 0][b_n] = packh2(bR0.x, bR0.y);
            Bs2[nxt][krb + 1][b_n] = packh2(bR0.z, bR0.w);
            Bs2[nxt][krb + 8][b_n] = packh2(bR1.x, bR1.y);
            Bs2[nxt][krb + 9][b_n] = packh2(bR1.z, bR1.w);
        }
        __syncthreads();
    }

    const int row0 = bm * 128 + wm * 32 + (lane >> 2);
    const int col0 = n0 + wn * 32 + ((lane & 3) << 1);
#pragma unroll
    for (int ms = 0; ms < 2; ++ms)
#pragma unroll
        for (int ns = 0; ns < 4; ++ns) {
            const int r   = row0 + ms * 16;
            const int col = col0 + ns * 8;
            *(float2*)&Cp[(long)r * ldc + col]       = make_float2(c[ms][ns][0], c[ms][ns][1]);
            *(float2*)&Cp[(long)(r + 8) * ldc + col] = make_float2(c[ms][ns][2], c[ms][ns][3]);
        }
}

// ---------------- pipelined fp16 GEMM with ldmatrix fragments ----------------
// A, B fp16 row-major k-contiguous. BM=BN=128, BK=32, 512 threads, warp tile 32x32.
// cp.async 4-stage; fragments via ldmatrix.m8n8.x4 (8 per warp-chunk instead of
// 32 LDS.32). RW=20 row stride: 8-row LDSM phases hit disjoint bank sets.
enum { P_QKV = 0, P_OUT = 1 };

#define S_STAGES 4
#define RW 20
#define A_STG_BYTES (128*RW*4)      // 10240
#define STG_BYTES   (2*A_STG_BYTES) // 20480
#define GA_SMEM (S_STAGES*STG_BYTES) // 81920

template<int MODE>
__global__ __launch_bounds__(512)
void gemm_a(const __half* __restrict__ A, const __half* __restrict__ Bm,
            void* __restrict__ Cp, const float* __restrict__ bias,
            int K, int lda, int ldb)
{
    extern __shared__ char smem[];
    const uint32_t sbase = smem_u32(smem);
    const int tid = threadIdx.x, lane = tid & 31, warp = tid >> 5;
    const int wm = warp & 3, wn = warp >> 2;
    const int bm = blockIdx.y, n0 = blockIdx.x * 128;

    const int srow = tid >> 2, sch = tid & 3;
    const __half* aSrc = A + (long)(bm * 128 + srow) * lda + sch * 8;
    const __half* bSrc = Bm + (long)(n0 + srow) * ldb + sch * 8;
    const uint32_t dstOff = srow * (RW * 4) + sch * 16;

    // ldmatrix lane addresses (byte offsets within a stage buffer)
    const int sub = lane >> 3, rL = lane & 7;
    uint32_t aOff[2], bOff[2];
#pragma unroll
    for (int ms = 0; ms < 2; ++ms)
        aOff[ms] = ((wm * 32 + ms * 16 + (sub & 1) * 8 + rL) * RW + (sub >> 1) * 4) * 4;
#pragma unroll
    for (int n2 = 0; n2 < 2; ++n2)
        bOff[n2] = ((wn * 32 + n2 * 16 + (sub >> 1) * 8 + rL) * RW + (sub & 1) * 4) * 4
                   + A_STG_BYTES;

    const int KT = K >> 5;
#pragma unroll
    for (int s = 0; s < S_STAGES - 1; ++s) {
        if (s < KT) {
            cp16(sbase + s * STG_BYTES + dstOff, aSrc + s * 32);
            cp16(sbase + s * STG_BYTES + A_STG_BYTES + dstOff, bSrc + s * 32);
        }
        asm volatile("cp.async.commit_group;" ::: "memory");
    }

    float c[2][4][4];
#pragma unroll
    for (int i = 0; i < 2; ++i)
#pragma unroll
        for (int j = 0; j < 4; ++j)
#pragma unroll
            for (int q = 0; q < 4; ++q) c[i][j][q] = 0.f;

    for (int kt = 0; kt < KT; ++kt) {
        asm volatile("cp.async.wait_group 2;" ::: "memory");
        __syncthreads();
        {
            const int s = kt + S_STAGES - 1;
            if (s < KT) {
                const int buf = s & (S_STAGES - 1);
                cp16(sbase + buf * STG_BYTES + dstOff, aSrc + (long)s * 32);
                cp16(sbase + buf * STG_BYTES + A_STG_BYTES + dstOff, bSrc + (long)s * 32);
            }
            asm volatile("cp.async.commit_group;" ::: "memory");
        }
        const uint32_t stg = sbase + (kt & 3) * STG_BYTES;
#pragma unroll
        for (int ks = 0; ks < 2; ++ks) {
            const uint32_t kadd = ks * 32;   // 8 words = 32 bytes
            uint32_t af[2][4], bf[4][2];
            ldsm4(af[0][0], af[0][1], af[0][2], af[0][3], stg + aOff[0] + kadd);
            ldsm4(af[1][0], af[1][1], af[1][2], af[1][3], stg + aOff[1] + kadd);
            ldsm4(bf[0][0], bf[0][1], bf[1][0], bf[1][1], stg + bOff[0] + kadd);
            ldsm4(bf[2][0], bf[2][1], bf[3][0], bf[3][1], stg + bOff[1] + kadd);
#pragma unroll
            for (int ms = 0; ms < 2; ++ms)
#pragma unroll
                for (int ns = 0; ns < 4; ++ns)
                    mma_f16(c[ms][ns], af[ms], bf[ns]);
        }
    }

    // epilogue
    const int row0 = bm * 128 + wm * 32 + (lane >> 2);
    const int col0 = n0 + wn * 32 + ((lane & 3) << 1);
#pragma unroll
    for (int ms = 0; ms < 2; ++ms)
#pragma unroll
        for (int ns = 0; ns < 4; ++ns) {
            const int r   = row0 + ms * 16;
            const int col = col0 + ns * 8;
            const float v0 = c[ms][ns][0], v1 = c[ms][ns][1];
            const float v2 = c[ms][ns][2], v3 = c[ms][ns][3];
            if (MODE == P_QKV) {
                const int dd = (bm >> 4) & 1;
                const float bb0 = bias[dd * JJ + col];
                const float bb1 = bias[dd * JJ + col + 1];
                __half2* O = (__half2*)Cp;
                O[((long)r * JJ + col) >> 1]       = __floats2half2_rn(v0 + bb0, v1 + bb1);
                O[((long)(r + 8) * JJ + col) >> 1] = __floats2half2_rn(v2 + bb0, v3 + bb1);
            } else {  // P_OUT: out[(b*C+col)*T + t]
                float* Of = (float*)Cp;
                const int b_ = r >> 11;
                const int t_ = r & (TT - 1);
                const float bb0 = bias[col], bb1 = bias[col + 1];
                float* o0 = Of + (long)(b_ * CC + col) * TT + t_;
                float* o1 = Of + (long)(b_ * CC + col + 1) * TT + t_;
                o0[0] = v0 + bb0; o1[0] = v1 + bb1;
                o0[8] = v2 + bb0; o1[8] = v3 + bb1;
            }
        }
}

// ---------------- attention (fp16 qkv -> fp16 ctx) ----------------
__global__ void attn_kernel()
{
    const int warp = threadIdx.x >> 5;
    const int lane = threadIdx.x & 31;
    const int n = blockIdx.x * 8 + warp;      // token
    const int b = n >> 11;
    const int t = n & (TT - 1);
    const __half2* r0 = (const __half2*)(g_qkvh + ((long)(b * 2 + 0) * TT + t) * JJ);
    const __half2* r1 = (const __half2*)(g_qkvh + ((long)(b * 2 + 1) * TT + t) * JJ);

    float s[4][2][2];
#pragma unroll
    for (int h = 0; h < 4; ++h) {
        float s00 = 0, s01 = 0, s10 = 0, s11 = 0;
#pragma unroll
        for (int j = 0; j < 2; ++j) {
            const int i2 = h * 64 + lane + 32 * j;
            const float2 q0 = __half22float2(r0[i2]);
            const float2 q1 = __half22float2(r1[i2]);
            const float2 k0 = __half22float2(r0[256 + i2]);
            const float2 k1 = __half22float2(r1[256 + i2]);
            s00 += q0.x * k0.x + q0.y * k0.y;
            s01 += q0.x * k1.x + q0.y * k1.y;
            s10 += q1.x * k0.x + q1.y * k0.y;
            s11 += q1.x * k1.x + q1.y * k1.y;
        }
        s[h][0][0] = s00; s[h][0][1] = s01; s[h][1][0] = s10; s[h][1][1] = s11;
    }
#pragma unroll
    for (int h = 0; h < 4; ++h)
#pragma unroll
        for (int d = 0; d < 2; ++d)
#pragma unroll
            for (int e = 0; e < 2; ++e)
                s[h][d][e] = warp_sum(s[h][d][e]);

    const float scale = 0.0883883476483184f;  // 1/sqrt(128)
    float p[4][2][2];
#pragma unroll
    for (int h = 0; h < 4; ++h)
#pragma unroll
        for (int d = 0; d < 2; ++d) {
            const float a  = s[h][d][0] * scale;
            const float bb = s[h][d][1] * scale;
            const float mx = fmaxf(a, bb);
            const float e0 = expf(a - mx), e1 = expf(bb - mx);
            const float inv = 1.0f / (e0 + e1);
            p[h][d][0] = e0 * inv; p[h][d][1] = e1 * inv;
        }

    __half2* crow = (__half2*)(g_ctxh + (long)n * 1024);
#pragma unroll
    for (int u = 0; u < 8; ++u) {
        const int j2 = lane + 32 * u;
        const int h = j2 >> 6;
        const float2 a0 = __half22float2(r0[512 + j2]);
        const float2 a1 = __half22float2(r1[512 + j2]);
        crow[j2] = __floats2half2_rn(p[h][0][0] * a0.x + p[h][0][1] * a1.x,
                                     p[h][0][0] * a0.y + p[h][0][1] * a1.y);
        crow[256 + j2] = __floats2half2_rn(p[h][1][0] * a0.x + p[h][1][1] * a1.x,
                                           p[h][1][0] * a0.y + p[h][1][1] * a1.y);
    }

    __shared__ float red[8][4];
    if (lane == 0) {
#pragma unroll
        for (int d = 0; d < 2; ++d)
#pragma unroll
            for (int e = 0; e < 2; ++e)
                red[warp][d * 2 + e] =
                    0.25f * (p[0][d][e] + p[1][d][e] + p[2][d][e] + p[3][d][e]);
    }
    __syncthreads();
    if (threadIdx.x < 4) {
        float acc = 0.f;
#pragma unroll
        for (int w = 0; w < 8; ++w) acc += red[w][threadIdx.x];
        atomicAdd(&g_att[b * 4 + threadIdx.x], acc);
    }
}

// ---------------- launch ----------------
extern "C" void kernel_launch(void* const* d_in, const int* in_sizes, int n_in,
                              void* d_out, int out_size)
{
    const float* x    = (const float*)d_in[0];
    const float* emb  = (const float*)d_in[1];
    const float* W1   = (const float*)d_in[2];
    const float* b1   = (const float*)d_in[3];
    const float* Wo   = (const float*)d_in[4];
    const float* bo   = (const float*)d_in[5];
    const float* Wp   = (const float*)d_in[6];
    const float* bp   = (const float*)d_in[7];
    const float* Wi   = (const float*)d_in[8];
    const float* bi   = (const float*)d_in[9];
    const float* Wout = (const float*)d_in[10];
    const float* bout = (const float*)d_in[11];
    float* out = (float*)d_out;

    void *p;
    float *p_WoT, *p_G0, *p_G1, *p_GT0, *p_GT1, *p_M, *p_bc, *p_qb;
    __half *p_xh, *p_w1h, *p_qkvh, *p_ctxh, *p_Mh;
    cudaGetSymbolAddress(&p, g_WoT);  p_WoT  = (float*)p;
    cudaGetSymbolAddress(&p, g_G0);   p_G0   = (float*)p;
    cudaGetSymbolAddress(&p, g_G1);   p_G1   = (float*)p;
    cudaGetSymbolAddress(&p, g_GT0);  p_GT0  = (float*)p;
    cudaGetSymbolAddress(&p, g_GT1);  p_GT1  = (float*)p;
    cudaGetSymbolAddress(&p, g_M);    p_M    = (float*)p;
    cudaGetSymbolAddress(&p, g_bc);   p_bc   = (float*)p;
    cudaGetSymbolAddress(&p, g_qb);   p_qb   = (float*)p;
    cudaGetSymbolAddress(&p, g_xh);   p_xh   = (__half*)p;
    cudaGetSymbolAddress(&p, g_w1h);  p_w1h  = (__half*)p;
    cudaGetSymbolAddress(&p, g_qkvh); p_qkvh = (__half*)p;
    cudaGetSymbolAddress(&p, g_ctxh); p_ctxh = (__half*)p;
    cudaGetSymbolAddress(&p, g_Mh);   p_Mh   = (__half*)p;

    cudaFuncSetAttribute(gemm_a<P_QKV>, cudaFuncAttributeMaxDynamicSharedMemorySize, GA_SMEM);
    cudaFuncSetAttribute(gemm_a<P_OUT>, cudaFuncAttributeMaxDynamicSharedMemorySize, GA_SMEM);

    // QKV path first (also puts gemm_a<P_QKV> at the ncu capture slot)
    xpose_kernel<<<dim3(64, 16, 32), dim3(32, 8)>>>(x);
    f2h_kernel<<<(JJ * CC / 4 + 255) / 256, 256>>>(W1, p_w1h, (long)JJ * CC);
    qb_kernel<<<384, 256>>>(W1, b1, emb);
    gemm_a<P_QKV><<<dim3(12, 512), 512, GA_SMEM>>>(p_xh, p_w1h, p_qkvh, p_qb, 512, 512, 512);

    zero_att_kernel<<<1, 64>>>();
    attn_kernel<<<4096, 256>>>();

    // fold chain + biases for the output GEMM
    ub_kernel<<<128, 256>>>(Wp, bp, Wi, bi, bo);
    bc_kernel<<<64, 256>>>(Wout, bout);
    transpose512<<<dim3(16, 16), dim3(32, 8)>>>(Wo, p_WoT);
    gemm_fold<<<dim3(4, 4), 512>>>(Wp, p_WoT, p_G0, 512, 512, 512, 512);
    gemm_fold<<<dim3(4, 4), 512>>>(Wi, p_WoT, p_G1, 512, 512, 512, 512);
    transpose512<<<dim3(16, 16), dim3(32, 8)>>>(p_G0, p_GT0);
    transpose512<<<dim3(16, 16), dim3(32, 8)>>>(p_G1, p_GT1);
    gemm_fold<<<dim3(4, 4), 512>>>(Wout,       p_GT0, p_M,       512, 1024, 512, 1024);
    gemm_fold<<<dim3(4, 4), 512>>>(Wout + 512, p_GT1, p_M + 512, 512, 1024, 512, 1024);
    f2h_kernel<<<(CC * 1024 / 4 + 255) / 256, 256>>>(p_M, p_Mh, (long)CC * 1024);

    // out = ctxh * Mh^T + bc, stored transposed to (B, C, T) fp32
    gemm_a<P_OUT><<<dim3(4, 256), 512, GA_SMEM>>>(p_ctxh, p_Mh, out, p_bc, 1024, 1024, 1024);

    if (out_size >= BB * CC * TT + BB * 4) {
        avg_out_kernel<<<1, 64>>>(out + (long)BB * CC * TT);
    }
}